// round 10
// baseline (speedup 1.0000x reference)
#include <cuda_runtime.h>
#include <cstdint>

#define N_NODES_MAX 50000
#define IN_FEATS 128
#define N_HIDDEN 128
#define N_CLASSES 64
#define DEG_STRIDE 96   // fixed slots per node; P(Poisson(12) >= 96) ~ 0
#define KC 32           // GEMM k-chunk

typedef unsigned long long ull;

// Scratch (no device allocation allowed).
__device__ float g_h[N_NODES_MAX * N_HIDDEN];
__device__ float g_agg[N_NODES_MAX * N_HIDDEN];
__device__ int   g_cur[N_NODES_MAX];                    // degree counters (zero-invariant)
__device__ ull   g_epack[(size_t)N_NODES_MAX * DEG_STRIDE];  // (w<<32|src) slots per node

__device__ __forceinline__ ull pack_edge(int s, float w) {
    return ((ull)__float_as_uint(w) << 32) | (unsigned)s;
}
__device__ __forceinline__ ull pack2(float lo, float hi) {
    ull r;
    asm("mov.b64 %0, {%1, %2};" : "=l"(r) : "f"(lo), "f"(hi));
    return r;
}

// ---------------- single-kernel CSR-lite build ----------------
__global__ void bin_kernel(const int* __restrict__ dst,
                           const int* __restrict__ src,
                           const float* __restrict__ w, int n_edges) {
    int t = blockIdx.x * blockDim.x + threadIdx.x;
    int e = t * 4;
    if (e + 4 <= n_edges) {
        int4 d = *reinterpret_cast<const int4*>(dst + e);
        int4 s = *reinterpret_cast<const int4*>(src + e);
        float4 ww = *reinterpret_cast<const float4*>(w + e);
        int p0 = atomicAdd(&g_cur[d.x], 1);
        int p1 = atomicAdd(&g_cur[d.y], 1);
        int p2 = atomicAdd(&g_cur[d.z], 1);
        int p3 = atomicAdd(&g_cur[d.w], 1);
        if (p0 < DEG_STRIDE) g_epack[(size_t)d.x * DEG_STRIDE + p0] = pack_edge(s.x, ww.x);
        if (p1 < DEG_STRIDE) g_epack[(size_t)d.y * DEG_STRIDE + p1] = pack_edge(s.y, ww.y);
        if (p2 < DEG_STRIDE) g_epack[(size_t)d.z * DEG_STRIDE + p2] = pack_edge(s.z, ww.z);
        if (p3 < DEG_STRIDE) g_epack[(size_t)d.w * DEG_STRIDE + p3] = pack_edge(s.w, ww.w);
    } else {
        for (int i = e; i < n_edges; i++) {
            int p = atomicAdd(&g_cur[dst[i]], 1);
            if (p < DEG_STRIDE) g_epack[(size_t)dst[i] * DEG_STRIDE + p] = pack_edge(src[i], w[i]);
        }
    }
}

// ---------------- dense linear: 2D-tiled f32x2 SGEMM ----------------
// 256 threads; tile M_TILE rows x F_OUT cols. Thread computes 8 rows (4 pairs)
// x 8 cols. H staged as row-pair ull, W staged pre-duplicated (w,w).
// Inner k-step: 6 LDS.128 + 32 FFMA2. No LDG, no movs in the hot loop.
template <int F_IN, int F_OUT, int M_TILE, bool RELU_IN>
__global__ void __launch_bounds__(256, 2)
linear_tile_kernel(const float* __restrict__ in,
                   const float* __restrict__ Wm,
                   const float* __restrict__ bv,
                   float* __restrict__ out, int n_rows) {
    constexpr int MP2 = M_TILE / 2;        // row pairs per block
    constexpr int TX  = F_OUT / 8;         // threads across columns
    constexpr int TY  = 256 / TX;
    constexpr int RPT = MP2 / TY;          // row pairs per thread (= 4)
    static_assert(RPT == 4, "tile math");
    constexpr int CG  = 256 / MP2;         // staging col-groups
    constexpr int KPT = KC / CG;           // k's staged per thread
    constexpr int C4  = F_IN / 4;

    __shared__ alignas(16) ull Hs[KC][MP2];
    __shared__ alignas(16) ull Ws[KC][F_OUT];

    const int tid  = threadIdx.x;
    const int row0 = blockIdx.x * M_TILE;
    const int tx   = tid % TX;
    const int ty   = tid / TX;

    ull acc[4][8];
    #pragma unroll
    for (int r = 0; r < 4; r++)
        #pragma unroll
        for (int c = 0; c < 8; c++) acc[r][c] = 0ull;

    const float4* in4 = reinterpret_cast<const float4*>(in);
    const int sp  = tid % MP2;             // staging row pair
    const int scg = tid / MP2;             // staging k-group
    const int ra  = row0 + 2 * sp;
    const int rb  = ra + 1;

    for (int kc = 0; kc < F_IN; kc += KC) {
        // ---- stage H (row pairs, ReLU folded) ----
        #pragma unroll
        for (int kk = 0; kk < KPT; kk += 4) {
            int k0 = scg * KPT + kk;
            float4 a = make_float4(0.f, 0.f, 0.f, 0.f);
            float4 b = make_float4(0.f, 0.f, 0.f, 0.f);
            if (ra < n_rows) a = in4[(size_t)ra * C4 + (kc + k0) / 4];
            if (rb < n_rows) b = in4[(size_t)rb * C4 + (kc + k0) / 4];
            if (RELU_IN) {
                a.x = fmaxf(a.x, 0.f); a.y = fmaxf(a.y, 0.f);
                a.z = fmaxf(a.z, 0.f); a.w = fmaxf(a.w, 0.f);
                b.x = fmaxf(b.x, 0.f); b.y = fmaxf(b.y, 0.f);
                b.z = fmaxf(b.z, 0.f); b.w = fmaxf(b.w, 0.f);
            }
            Hs[k0 + 0][sp] = pack2(a.x, b.x);
            Hs[k0 + 1][sp] = pack2(a.y, b.y);
            Hs[k0 + 2][sp] = pack2(a.z, b.z);
            Hs[k0 + 3][sp] = pack2(a.w, b.w);
        }
        // ---- stage W (duplicated pairs) ----
        #pragma unroll
        for (int idx = tid; idx < KC * F_OUT; idx += 256) {
            int k = idx / F_OUT;
            int c = idx - k * F_OUT;
            float wv = __ldg(Wm + (size_t)(kc + k) * F_OUT + c);
            Ws[k][c] = pack2(wv, wv);
        }
        __syncthreads();

        // ---- compute ----
        #pragma unroll 2
        for (int k = 0; k < KC; k++) {
            ulonglong2 h01 = *reinterpret_cast<const ulonglong2*>(&Hs[k][ty * 4]);
            ulonglong2 h23 = *reinterpret_cast<const ulonglong2*>(&Hs[k][ty * 4 + 2]);
            ulonglong2 wA = *reinterpret_cast<const ulonglong2*>(&Ws[k][tx * 8]);
            ulonglong2 wB = *reinterpret_cast<const ulonglong2*>(&Ws[k][tx * 8 + 2]);
            ulonglong2 wC = *reinterpret_cast<const ulonglong2*>(&Ws[k][tx * 8 + 4]);
            ulonglong2 wD = *reinterpret_cast<const ulonglong2*>(&Ws[k][tx * 8 + 6]);
            ull hr[4] = {h01.x, h01.y, h23.x, h23.y};
            ull wc[8] = {wA.x, wA.y, wB.x, wB.y, wC.x, wC.y, wD.x, wD.y};
            #pragma unroll
            for (int r = 0; r < 4; r++)
                #pragma unroll
                for (int c = 0; c < 8; c++)
                    asm("fma.rn.f32x2 %0, %1, %2, %0;"
                        : "+l"(acc[r][c]) : "l"(hr[r]), "l"(wc[c]));
        }
        __syncthreads();
    }

    // ---- bias + store ----
    float bb[8];
    #pragma unroll
    for (int c = 0; c < 8; c++) bb[c] = __ldg(bv + tx * 8 + c);

    #pragma unroll
    for (int rp = 0; rp < 4; rp++) {
        int re = row0 + (ty * 4 + rp) * 2;  // even row
        float2 f[8];
        #pragma unroll
        for (int c = 0; c < 8; c++) f[c] = *reinterpret_cast<float2*>(&acc[rp][c]);
        if (re < n_rows) {
            float4 lo = make_float4(f[0].x + bb[0], f[1].x + bb[1], f[2].x + bb[2], f[3].x + bb[3]);
            float4 hi = make_float4(f[4].x + bb[4], f[5].x + bb[5], f[6].x + bb[6], f[7].x + bb[7]);
            float4* op = reinterpret_cast<float4*>(out + (size_t)re * F_OUT + tx * 8);
            op[0] = lo; op[1] = hi;
        }
        if (re + 1 < n_rows) {
            float4 lo = make_float4(f[0].y + bb[0], f[1].y + bb[1], f[2].y + bb[2], f[3].y + bb[3]);
            float4 hi = make_float4(f[4].y + bb[4], f[5].y + bb[5], f[6].y + bb[6], f[7].y + bb[7]);
            float4* op = reinterpret_cast<float4*>(out + (size_t)(re + 1) * F_OUT + tx * 8);
            op[0] = lo; op[1] = hi;
        }
    }
}

// ---------------- gather aggregation (MLP=4, strided slots) ----------------
template <int F, bool ZERO_CUR>
__global__ void gather_kernel(const float* __restrict__ h,
                              float* __restrict__ out, int n_nodes) {
    constexpr int LANES = F / 4;  // 32 (F=128) or 16 (F=64)
    const int tid = blockIdx.x * blockDim.x + threadIdx.x;
    const int node = tid / LANES;
    const int lane = tid - node * LANES;
    if (node >= n_nodes) return;

    const int wl = threadIdx.x & 31;
    const unsigned seg_mask = (LANES == 32) ? 0xffffffffu
                                            : (0xffffu << (wl & 16));

    int deg = __ldg(&g_cur[node]);
    if (deg > DEG_STRIDE) deg = DEG_STRIDE;
    if (ZERO_CUR && lane == 0) g_cur[node] = 0;
    const size_t beg = (size_t)node * DEG_STRIDE;
    const int cnt = deg < LANES ? deg : LANES;

    ull mymeta = 0;
    if (lane < cnt) mymeta = __ldg(&g_epack[beg + lane]);

    const float4* h4 = reinterpret_cast<const float4*>(h);
    float4 accA = make_float4(0.f, 0.f, 0.f, 0.f);
    float4 accB = make_float4(0.f, 0.f, 0.f, 0.f);

    int k = 0;
    for (; k + 4 <= cnt; k += 4) {
        ull m0 = __shfl_sync(seg_mask, mymeta, k + 0, LANES);
        ull m1 = __shfl_sync(seg_mask, mymeta, k + 1, LANES);
        ull m2 = __shfl_sync(seg_mask, mymeta, k + 2, LANES);
        ull m3 = __shfl_sync(seg_mask, mymeta, k + 3, LANES);
        float w0 = __uint_as_float((unsigned)(m0 >> 32));
        float w1 = __uint_as_float((unsigned)(m1 >> 32));
        float w2 = __uint_as_float((unsigned)(m2 >> 32));
        float w3 = __uint_as_float((unsigned)(m3 >> 32));
        float4 v0 = __ldg(h4 + (size_t)(unsigned)m0 * LANES + lane);
        float4 v1 = __ldg(h4 + (size_t)(unsigned)m1 * LANES + lane);
        float4 v2 = __ldg(h4 + (size_t)(unsigned)m2 * LANES + lane);
        float4 v3 = __ldg(h4 + (size_t)(unsigned)m3 * LANES + lane);
        accA.x += v0.x * w0; accA.y += v0.y * w0; accA.z += v0.z * w0; accA.w += v0.w * w0;
        accB.x += v1.x * w1; accB.y += v1.y * w1; accB.z += v1.z * w1; accB.w += v1.w * w1;
        accA.x += v2.x * w2; accA.y += v2.y * w2; accA.z += v2.z * w2; accA.w += v2.w * w2;
        accB.x += v3.x * w3; accB.y += v3.y * w3; accB.z += v3.z * w3; accB.w += v3.w * w3;
    }
    for (; k < cnt; k++) {
        ull m = __shfl_sync(seg_mask, mymeta, k, LANES);
        float w0 = __uint_as_float((unsigned)(m >> 32));
        float4 v0 = __ldg(h4 + (size_t)(unsigned)m * LANES + lane);
        accA.x += v0.x * w0; accA.y += v0.y * w0;
        accA.z += v0.z * w0; accA.w += v0.w * w0;
    }
    for (int j = LANES; j < deg; j++) {
        ull m = __ldg(&g_epack[beg + j]);
        float w0 = __uint_as_float((unsigned)(m >> 32));
        float4 v0 = __ldg(h4 + (size_t)(unsigned)m * LANES + lane);
        accB.x += v0.x * w0; accB.y += v0.y * w0;
        accB.z += v0.z * w0; accB.w += v0.w * w0;
    }

    accA.x += accB.x; accA.y += accB.y; accA.z += accB.z; accA.w += accB.w;
    reinterpret_cast<float4*>(out)[(size_t)node * LANES + lane] = accA;
}

extern "C" void kernel_launch(void* const* d_in, const int* in_sizes, int n_in,
                              void* d_out, int out_size) {
    const float* x   = (const float*)d_in[0];
    const float* w   = (const float*)d_in[1];
    const int*   src = (const int*)d_in[2];
    const int*   dst = (const int*)d_in[3];
    const float* W1  = (const float*)d_in[4];
    const float* b1  = (const float*)d_in[5];
    const float* W2  = (const float*)d_in[6];
    const float* b2  = (const float*)d_in[7];
    const float* W3  = (const float*)d_in[8];
    const float* b3  = (const float*)d_in[9];
    float* out = (float*)d_out;

    const int n_nodes = in_sizes[0] / IN_FEATS;
    const int n_edges = in_sizes[1];

    float *h_buf = nullptr, *agg_buf = nullptr;
    cudaGetSymbolAddress((void**)&h_buf, g_h);
    cudaGetSymbolAddress((void**)&agg_buf, g_agg);

    static cudaStream_t s2 = nullptr;
    static cudaEvent_t ev_fork = nullptr, ev_join = nullptr;
    if (!s2) {
        cudaStreamCreateWithFlags(&s2, cudaStreamNonBlocking);
        cudaEventCreateWithFlags(&ev_fork, cudaEventDisableTiming);
        cudaEventCreateWithFlags(&ev_join, cudaEventDisableTiming);
    }

    const int gemm128_blocks = (n_nodes + 127) / 128;
    const int gemm64_blocks  = (n_nodes + 255) / 256;
    const int g128_blocks = (n_nodes * (N_HIDDEN / 4) + 255) / 256;
    const int g64_blocks  = (n_nodes * (N_CLASSES / 4) + 255) / 256;
    const int bin_blocks  = ((n_edges + 3) / 4 + 255) / 256;

    // Fork: bin on s2 overlapping layer-1 GEMM on the main stream.
    cudaEventRecord(ev_fork, 0);
    cudaStreamWaitEvent(s2, ev_fork, 0);

    bin_kernel<<<bin_blocks, 256, 0, s2>>>(dst, src, w, n_edges);            // 1

    linear_tile_kernel<IN_FEATS, N_HIDDEN, 128, false>
        <<<gemm128_blocks, 256>>>(x, W1, b1, h_buf, n_nodes);                // 2

    cudaEventRecord(ev_join, s2);
    cudaStreamWaitEvent(0, ev_join, 0);

    gather_kernel<N_HIDDEN, false><<<g128_blocks, 256>>>(h_buf, agg_buf, n_nodes);  // 3

    linear_tile_kernel<N_HIDDEN, N_HIDDEN, 128, true>
        <<<gemm128_blocks, 256>>>(agg_buf, W2, b2, h_buf, n_nodes);          // 4 <- profiled
    gather_kernel<N_HIDDEN, false><<<g128_blocks, 256>>>(h_buf, agg_buf, n_nodes);  // 5

    linear_tile_kernel<N_HIDDEN, N_CLASSES, 256, true>
        <<<gemm64_blocks, 256>>>(agg_buf, W3, b3, h_buf, n_nodes);           // 6
    gather_kernel<N_CLASSES, true><<<g64_blocks, 256>>>(h_buf, out, n_nodes);       // 7 (zeroes g_cur)
}

// round 11
// speedup vs baseline: 1.8368x; 1.8368x over previous
#include <cuda_runtime.h>
#include <cstdint>

#define N_NODES_MAX 50000
#define IN_FEATS 128
#define N_HIDDEN 128
#define N_CLASSES 64
#define DEG_STRIDE 96   // fixed slots per node; P(Poisson(12) >= 96) ~ 0
#define KC 32           // GEMM k-chunk

typedef unsigned long long ull;

// Scratch (no device allocation allowed).
__device__ float g_h[N_NODES_MAX * N_HIDDEN];
__device__ float g_agg[N_NODES_MAX * N_HIDDEN];
__device__ int   g_cur[N_NODES_MAX];                    // degree counters (zero-invariant)
__device__ ull   g_epack[(size_t)N_NODES_MAX * DEG_STRIDE];  // (w<<32|src) slots per node

__device__ __forceinline__ ull pack_edge(int s, float w) {
    return ((ull)__float_as_uint(w) << 32) | (unsigned)s;
}
__device__ __forceinline__ ull pack2(float lo, float hi) {
    ull r;
    asm("mov.b64 %0, {%1, %2};" : "=l"(r) : "f"(lo), "f"(hi));
    return r;
}

// ---------------- single-kernel CSR-lite build ----------------
__global__ void bin_kernel(const int* __restrict__ dst,
                           const int* __restrict__ src,
                           const float* __restrict__ w, int n_edges) {
    int t = blockIdx.x * blockDim.x + threadIdx.x;
    int e = t * 4;
    if (e + 4 <= n_edges) {
        int4 d = *reinterpret_cast<const int4*>(dst + e);
        int4 s = *reinterpret_cast<const int4*>(src + e);
        float4 ww = *reinterpret_cast<const float4*>(w + e);
        int p0 = atomicAdd(&g_cur[d.x], 1);
        int p1 = atomicAdd(&g_cur[d.y], 1);
        int p2 = atomicAdd(&g_cur[d.z], 1);
        int p3 = atomicAdd(&g_cur[d.w], 1);
        if (p0 < DEG_STRIDE) g_epack[(size_t)d.x * DEG_STRIDE + p0] = pack_edge(s.x, ww.x);
        if (p1 < DEG_STRIDE) g_epack[(size_t)d.y * DEG_STRIDE + p1] = pack_edge(s.y, ww.y);
        if (p2 < DEG_STRIDE) g_epack[(size_t)d.z * DEG_STRIDE + p2] = pack_edge(s.z, ww.z);
        if (p3 < DEG_STRIDE) g_epack[(size_t)d.w * DEG_STRIDE + p3] = pack_edge(s.w, ww.w);
    } else {
        for (int i = e; i < n_edges; i++) {
            int p = atomicAdd(&g_cur[dst[i]], 1);
            if (p < DEG_STRIDE) g_epack[(size_t)dst[i] * DEG_STRIDE + p] = pack_edge(src[i], w[i]);
        }
    }
}

// ---------------- dense linear: 2D-tiled f32x2 SGEMM, conflict-free W ----------------
// 256 threads; tile M_TILE rows x F_OUT cols. Thread (tx,ty) computes 8 rows
// (4 pairs) x 8 cols, columns interleaved: {g*2TX + 2tx, +1} for g = 0..3.
// W staged as ulonglong2 Ws2[k][g][tx] -> W reads are 16 lanes x consecutive
// 16B = conflict-free. H reads are warp-broadcast. Inner k-step: 6 LDS.128 +
// 32 FFMA2, FFMA2-issue bound.
template <int F_IN, int F_OUT, int M_TILE, bool RELU_IN>
__global__ void __launch_bounds__(256, 2)
linear_tile_kernel(const float* __restrict__ in,
                   const float* __restrict__ Wm,
                   const float* __restrict__ bv,
                   float* __restrict__ out, int n_rows) {
    constexpr int MP2 = M_TILE / 2;        // row pairs per block
    constexpr int TX  = F_OUT / 8;         // threads across columns
    constexpr int TY  = 256 / TX;
    static_assert(MP2 / TY == 4, "tile math");
    constexpr int GS  = 2 * TX;            // column-group stride
    constexpr int CG  = 256 / MP2;         // staging col-groups
    constexpr int KPT = KC / CG;           // k's staged per thread
    constexpr int C4  = F_IN / 4;

    __shared__ alignas(16) ull Hs[KC][MP2];
    __shared__ alignas(16) ulonglong2 Ws2[KC][4][TX];

    const int tid  = threadIdx.x;
    const int row0 = blockIdx.x * M_TILE;
    const int tx   = tid % TX;
    const int ty   = tid / TX;

    ull acc[4][8];
    #pragma unroll
    for (int r = 0; r < 4; r++)
        #pragma unroll
        for (int c = 0; c < 8; c++) acc[r][c] = 0ull;

    const float4* in4 = reinterpret_cast<const float4*>(in);
    const int sp  = tid % MP2;             // staging row pair
    const int scg = tid / MP2;             // staging k-group
    const int ra  = row0 + 2 * sp;
    const int rb  = ra + 1;

    for (int kc = 0; kc < F_IN; kc += KC) {
        // ---- stage H (row pairs, ReLU folded) ----
        #pragma unroll
        for (int kk = 0; kk < KPT; kk += 4) {
            int k0 = scg * KPT + kk;
            float4 a = make_float4(0.f, 0.f, 0.f, 0.f);
            float4 b = make_float4(0.f, 0.f, 0.f, 0.f);
            if (ra < n_rows) a = in4[(size_t)ra * C4 + (kc + k0) / 4];
            if (rb < n_rows) b = in4[(size_t)rb * C4 + (kc + k0) / 4];
            if (RELU_IN) {
                a.x = fmaxf(a.x, 0.f); a.y = fmaxf(a.y, 0.f);
                a.z = fmaxf(a.z, 0.f); a.w = fmaxf(a.w, 0.f);
                b.x = fmaxf(b.x, 0.f); b.y = fmaxf(b.y, 0.f);
                b.z = fmaxf(b.z, 0.f); b.w = fmaxf(b.w, 0.f);
            }
            Hs[k0 + 0][sp] = pack2(a.x, b.x);
            Hs[k0 + 1][sp] = pack2(a.y, b.y);
            Hs[k0 + 2][sp] = pack2(a.z, b.z);
            Hs[k0 + 3][sp] = pack2(a.w, b.w);
        }
        // ---- stage W: Ws2[k][g][t] = dup pairs of cols (g*GS+2t, +1) ----
        #pragma unroll
        for (int idx = tid; idx < KC * 4 * TX; idx += 256) {
            int k   = idx / (4 * TX);
            int rem = idx - k * (4 * TX);
            int g   = rem / TX;
            int t   = rem - g * TX;
            float2 wv = *reinterpret_cast<const float2*>(
                Wm + (size_t)(kc + k) * F_OUT + g * GS + 2 * t);
            ulonglong2 d2;
            d2.x = pack2(wv.x, wv.x);
            d2.y = pack2(wv.y, wv.y);
            Ws2[k][g][t] = d2;
        }
        __syncthreads();

        // ---- compute: 6 conflict-free LDS.128 + 32 FFMA2 per k ----
        #pragma unroll 2
        for (int k = 0; k < KC; k++) {
            ulonglong2 h01 = *reinterpret_cast<const ulonglong2*>(&Hs[k][ty * 4]);
            ulonglong2 h23 = *reinterpret_cast<const ulonglong2*>(&Hs[k][ty * 4 + 2]);
            ulonglong2 w0 = Ws2[k][0][tx];
            ulonglong2 w1 = Ws2[k][1][tx];
            ulonglong2 w2 = Ws2[k][2][tx];
            ulonglong2 w3 = Ws2[k][3][tx];
            ull hr[4] = {h01.x, h01.y, h23.x, h23.y};
            ull wc[8] = {w0.x, w0.y, w1.x, w1.y, w2.x, w2.y, w3.x, w3.y};
            #pragma unroll
            for (int r = 0; r < 4; r++)
                #pragma unroll
                for (int c = 0; c < 8; c++)
                    asm("fma.rn.f32x2 %0, %1, %2, %0;"
                        : "+l"(acc[r][c]) : "l"(hr[r]), "l"(wc[c]));
        }
        __syncthreads();
    }

    // ---- bias + store (float2 per column pair, coalesced across tx) ----
    float2 bb[4];
    #pragma unroll
    for (int g = 0; g < 4; g++)
        bb[g] = *reinterpret_cast<const float2*>(bv + g * GS + 2 * tx);

    #pragma unroll
    for (int rp = 0; rp < 4; rp++) {
        int re = row0 + (ty * 4 + rp) * 2;  // even row
        #pragma unroll
        for (int g = 0; g < 4; g++) {
            float2 c0 = *reinterpret_cast<float2*>(&acc[rp][2 * g]);      // (even, odd) col0
            float2 c1 = *reinterpret_cast<float2*>(&acc[rp][2 * g + 1]);  // (even, odd) col1
            int col = g * GS + 2 * tx;
            if (re < n_rows) {
                float2 v = make_float2(c0.x + bb[g].x, c1.x + bb[g].y);
                *reinterpret_cast<float2*>(out + (size_t)re * F_OUT + col) = v;
            }
            if (re + 1 < n_rows) {
                float2 v = make_float2(c0.y + bb[g].x, c1.y + bb[g].y);
                *reinterpret_cast<float2*>(out + (size_t)(re + 1) * F_OUT + col) = v;
            }
        }
    }
}

// ---------------- gather aggregation (MLP=4, strided slots) ----------------
template <int F, bool ZERO_CUR>
__global__ void gather_kernel(const float* __restrict__ h,
                              float* __restrict__ out, int n_nodes) {
    constexpr int LANES = F / 4;  // 32 (F=128) or 16 (F=64)
    const int tid = blockIdx.x * blockDim.x + threadIdx.x;
    const int node = tid / LANES;
    const int lane = tid - node * LANES;
    if (node >= n_nodes) return;

    const int wl = threadIdx.x & 31;
    const unsigned seg_mask = (LANES == 32) ? 0xffffffffu
                                            : (0xffffu << (wl & 16));

    int deg = __ldg(&g_cur[node]);
    if (deg > DEG_STRIDE) deg = DEG_STRIDE;
    if (ZERO_CUR && lane == 0) g_cur[node] = 0;
    const size_t beg = (size_t)node * DEG_STRIDE;
    const int cnt = deg < LANES ? deg : LANES;

    ull mymeta = 0;
    if (lane < cnt) mymeta = __ldg(&g_epack[beg + lane]);

    const float4* h4 = reinterpret_cast<const float4*>(h);
    float4 accA = make_float4(0.f, 0.f, 0.f, 0.f);
    float4 accB = make_float4(0.f, 0.f, 0.f, 0.f);

    int k = 0;
    for (; k + 4 <= cnt; k += 4) {
        ull m0 = __shfl_sync(seg_mask, mymeta, k + 0, LANES);
        ull m1 = __shfl_sync(seg_mask, mymeta, k + 1, LANES);
        ull m2 = __shfl_sync(seg_mask, mymeta, k + 2, LANES);
        ull m3 = __shfl_sync(seg_mask, mymeta, k + 3, LANES);
        float w0 = __uint_as_float((unsigned)(m0 >> 32));
        float w1 = __uint_as_float((unsigned)(m1 >> 32));
        float w2 = __uint_as_float((unsigned)(m2 >> 32));
        float w3 = __uint_as_float((unsigned)(m3 >> 32));
        float4 v0 = __ldg(h4 + (size_t)(unsigned)m0 * LANES + lane);
        float4 v1 = __ldg(h4 + (size_t)(unsigned)m1 * LANES + lane);
        float4 v2 = __ldg(h4 + (size_t)(unsigned)m2 * LANES + lane);
        float4 v3 = __ldg(h4 + (size_t)(unsigned)m3 * LANES + lane);
        accA.x += v0.x * w0; accA.y += v0.y * w0; accA.z += v0.z * w0; accA.w += v0.w * w0;
        accB.x += v1.x * w1; accB.y += v1.y * w1; accB.z += v1.z * w1; accB.w += v1.w * w1;
        accA.x += v2.x * w2; accA.y += v2.y * w2; accA.z += v2.z * w2; accA.w += v2.w * w2;
        accB.x += v3.x * w3; accB.y += v3.y * w3; accB.z += v3.z * w3; accB.w += v3.w * w3;
    }
    for (; k < cnt; k++) {
        ull m = __shfl_sync(seg_mask, mymeta, k, LANES);
        float w0 = __uint_as_float((unsigned)(m >> 32));
        float4 v0 = __ldg(h4 + (size_t)(unsigned)m * LANES + lane);
        accA.x += v0.x * w0; accA.y += v0.y * w0;
        accA.z += v0.z * w0; accA.w += v0.w * w0;
    }
    for (int j = LANES; j < deg; j++) {
        ull m = __ldg(&g_epack[beg + j]);
        float w0 = __uint_as_float((unsigned)(m >> 32));
        float4 v0 = __ldg(h4 + (size_t)(unsigned)m * LANES + lane);
        accB.x += v0.x * w0; accB.y += v0.y * w0;
        accB.z += v0.z * w0; accB.w += v0.w * w0;
    }

    accA.x += accB.x; accA.y += accB.y; accA.z += accB.z; accA.w += accB.w;
    reinterpret_cast<float4*>(out)[(size_t)node * LANES + lane] = accA;
}

extern "C" void kernel_launch(void* const* d_in, const int* in_sizes, int n_in,
                              void* d_out, int out_size) {
    const float* x   = (const float*)d_in[0];
    const float* w   = (const float*)d_in[1];
    const int*   src = (const int*)d_in[2];
    const int*   dst = (const int*)d_in[3];
    const float* W1  = (const float*)d_in[4];
    const float* b1  = (const float*)d_in[5];
    const float* W2  = (const float*)d_in[6];
    const float* b2  = (const float*)d_in[7];
    const float* W3  = (const float*)d_in[8];
    const float* b3  = (const float*)d_in[9];
    float* out = (float*)d_out;

    const int n_nodes = in_sizes[0] / IN_FEATS;
    const int n_edges = in_sizes[1];

    float *h_buf = nullptr, *agg_buf = nullptr;
    cudaGetSymbolAddress((void**)&h_buf, g_h);
    cudaGetSymbolAddress((void**)&agg_buf, g_agg);

    static cudaStream_t s2 = nullptr;
    static cudaEvent_t ev_fork = nullptr, ev_join = nullptr;
    if (!s2) {
        cudaStreamCreateWithFlags(&s2, cudaStreamNonBlocking);
        cudaEventCreateWithFlags(&ev_fork, cudaEventDisableTiming);
        cudaEventCreateWithFlags(&ev_join, cudaEventDisableTiming);
    }

    const int gemm128_blocks = (n_nodes + 127) / 128;
    const int gemm64_blocks  = (n_nodes + 255) / 256;
    const int g128_blocks = (n_nodes * (N_HIDDEN / 4) + 255) / 256;
    const int g64_blocks  = (n_nodes * (N_CLASSES / 4) + 255) / 256;
    const int bin_blocks  = ((n_edges + 3) / 4 + 255) / 256;

    // Fork: bin on s2 overlapping layer-1 GEMM on the main stream.
    cudaEventRecord(ev_fork, 0);
    cudaStreamWaitEvent(s2, ev_fork, 0);

    bin_kernel<<<bin_blocks, 256, 0, s2>>>(dst, src, w, n_edges);            // 1

    linear_tile_kernel<IN_FEATS, N_HIDDEN, 128, false>
        <<<gemm128_blocks, 256>>>(x, W1, b1, h_buf, n_nodes);                // 2

    cudaEventRecord(ev_join, s2);
    cudaStreamWaitEvent(0, ev_join, 0);

    gather_kernel<N_HIDDEN, false><<<g128_blocks, 256>>>(h_buf, agg_buf, n_nodes);  // 3

    linear_tile_kernel<N_HIDDEN, N_HIDDEN, 128, true>
        <<<gemm128_blocks, 256>>>(agg_buf, W2, b2, h_buf, n_nodes);          // 4 <- profiled
    gather_kernel<N_HIDDEN, false><<<g128_blocks, 256>>>(h_buf, agg_buf, n_nodes);  // 5

    linear_tile_kernel<N_HIDDEN, N_CLASSES, 256, true>
        <<<gemm64_blocks, 256>>>(agg_buf, W3, b3, h_buf, n_nodes);           // 6
    gather_kernel<N_CLASSES, true><<<g64_blocks, 256>>>(h_buf, out, n_nodes);       // 7 (zeroes g_cur)
}

// round 12
// speedup vs baseline: 2.4254x; 1.3205x over previous
#include <cuda_runtime.h>
#include <cstdint>

#define N_NODES_MAX 50000
#define IN_FEATS 128
#define N_HIDDEN 128
#define N_CLASSES 64
#define DEG_STRIDE 96
#define KC 32
#define HS_STRIDE 44   // bank-conflict-free for STS.128 staging + frag LDS

typedef unsigned long long ull;

__device__ float g_h[N_NODES_MAX * N_HIDDEN];
__device__ float g_agg[N_NODES_MAX * N_HIDDEN];
__device__ int   g_cur[N_NODES_MAX];
__device__ ull   g_epack[(size_t)N_NODES_MAX * DEG_STRIDE];

__device__ __forceinline__ ull pack_edge(int s, float w) {
    return ((ull)__float_as_uint(w) << 32) | (unsigned)s;
}
__device__ __forceinline__ ull pack2(float lo, float hi) {
    ull r;
    asm("mov.b64 %0, {%1, %2};" : "=l"(r) : "f"(lo), "f"(hi));
    return r;
}
__device__ __forceinline__ unsigned to_tf32(float f) {
    unsigned u;
    asm("cvt.rna.tf32.f32 %0, %1;" : "=r"(u) : "f"(f));
    return u;
}

// ---------------- single-kernel CSR-lite build ----------------
__global__ void bin_kernel(const int* __restrict__ dst,
                           const int* __restrict__ src,
                           const float* __restrict__ w, int n_edges) {
    int t = blockIdx.x * blockDim.x + threadIdx.x;
    int e = t * 4;
    if (e + 4 <= n_edges) {
        int4 d = *reinterpret_cast<const int4*>(dst + e);
        int4 s = *reinterpret_cast<const int4*>(src + e);
        float4 ww = *reinterpret_cast<const float4*>(w + e);
        int p0 = atomicAdd(&g_cur[d.x], 1);
        int p1 = atomicAdd(&g_cur[d.y], 1);
        int p2 = atomicAdd(&g_cur[d.z], 1);
        int p3 = atomicAdd(&g_cur[d.w], 1);
        if (p0 < DEG_STRIDE) g_epack[(size_t)d.x * DEG_STRIDE + p0] = pack_edge(s.x, ww.x);
        if (p1 < DEG_STRIDE) g_epack[(size_t)d.y * DEG_STRIDE + p1] = pack_edge(s.y, ww.y);
        if (p2 < DEG_STRIDE) g_epack[(size_t)d.z * DEG_STRIDE + p2] = pack_edge(s.z, ww.z);
        if (p3 < DEG_STRIDE) g_epack[(size_t)d.w * DEG_STRIDE + p3] = pack_edge(s.w, ww.w);
    } else {
        for (int i = e; i < n_edges; i++) {
            int p = atomicAdd(&g_cur[dst[i]], 1);
            if (p < DEG_STRIDE) g_epack[(size_t)dst[i] * DEG_STRIDE + p] = pack_edge(src[i], w[i]);
        }
    }
}

// ---------------- tf32 tensor-core linear: 128 x 128, K = 128 ----------------
// 256 threads = 8 warps (4 m-groups x 2 n-groups); warp tile 32m x 64n.
// Per k8-step/warp: 8 LDS.32 (A frags) + 8 LDS.64 (B frags) + 16 mma.
template <bool RELU_IN>
__global__ void __launch_bounds__(256, 2)
linear_tf32_kernel(const float* __restrict__ in,
                   const float* __restrict__ Wm,
                   const float* __restrict__ bv,
                   float* __restrict__ out, int n_rows) {
    constexpr int F = 128;
    __shared__ unsigned Hs[128 * HS_STRIDE];       // tf32 H tile, row-major, stride 44
    __shared__ uint2    Bf[4][16][32];             // B frags: [k8][n-frag][lane]

    const int tid  = threadIdx.x;
    const int row0 = blockIdx.x * 128;
    const int wid  = tid >> 5;
    const int lane = tid & 31;
    const int g    = lane >> 2;
    const int t    = lane & 3;
    const int mw   = wid & 3;                      // m-group (32 rows)
    const int nw   = wid >> 2;                     // n-group (64 cols)

    float acc[2][8][4];
    #pragma unroll
    for (int mf = 0; mf < 2; mf++)
        #pragma unroll
        for (int nf = 0; nf < 8; nf++)
            #pragma unroll
            for (int c = 0; c < 4; c++) acc[mf][nf][c] = 0.f;

    const float4* in4 = reinterpret_cast<const float4*>(in);

    for (int kc = 0; kc < F; kc += KC) {
        // ---- stage H tile (coalesced LDG, ReLU + tf32 cvt, STS.128) ----
        #pragma unroll
        for (int i = 0; i < 4; i++) {
            int idx = tid + i * 256;               // 1024 float4 entries
            int c4  = idx & 7;
            int row = idx >> 3;
            float4 v = make_float4(0.f, 0.f, 0.f, 0.f);
            if (row0 + row < n_rows)
                v = in4[(size_t)(row0 + row) * (F / 4) + (kc >> 2) + c4];
            if (RELU_IN) {
                v.x = fmaxf(v.x, 0.f); v.y = fmaxf(v.y, 0.f);
                v.z = fmaxf(v.z, 0.f); v.w = fmaxf(v.w, 0.f);
            }
            uint4 u;
            u.x = to_tf32(v.x); u.y = to_tf32(v.y);
            u.z = to_tf32(v.z); u.w = to_tf32(v.w);
            *reinterpret_cast<uint4*>(&Hs[row * HS_STRIDE + c4 * 4]) = u;
        }
        // ---- stage B frags: Bf[kk][nf][lane] = {W[k+t][n], W[k+t+4][n]} ----
        #pragma unroll
        for (int i = 0; i < 8; i++) {
            int idx = tid + i * 256;               // 2048 entries
            int ln  = idx & 31;
            int nf  = (idx >> 5) & 15;
            int kk  = idx >> 9;
            int gg  = ln >> 2, tt = ln & 3;
            int krow = kc + kk * 8 + tt;
            int col  = nf * 8 + gg;
            uint2 b;
            b.x = to_tf32(__ldg(Wm + (size_t)krow * F + col));
            b.y = to_tf32(__ldg(Wm + (size_t)(krow + 4) * F + col));
            Bf[kk][nf][ln] = b;
        }
        __syncthreads();

        // ---- compute ----
        #pragma unroll
        for (int kk = 0; kk < 4; kk++) {
            unsigned a[2][4];
            #pragma unroll
            for (int mf = 0; mf < 2; mf++) {
                int mbase = (mw * 32 + mf * 16 + g) * HS_STRIDE + kk * 8;
                a[mf][0] = Hs[mbase + t];
                a[mf][1] = Hs[mbase + 8 * HS_STRIDE + t];
                a[mf][2] = Hs[mbase + t + 4];
                a[mf][3] = Hs[mbase + 8 * HS_STRIDE + t + 4];
            }
            uint2 b[8];
            #pragma unroll
            for (int nf = 0; nf < 8; nf++) b[nf] = Bf[kk][nw * 8 + nf][lane];
            #pragma unroll
            for (int mf = 0; mf < 2; mf++)
                #pragma unroll
                for (int nf = 0; nf < 8; nf++)
                    asm volatile(
                        "mma.sync.aligned.m16n8k8.row.col.f32.tf32.tf32.f32 "
                        "{%0,%1,%2,%3}, {%4,%5,%6,%7}, {%8,%9}, {%0,%1,%2,%3};\n"
                        : "+f"(acc[mf][nf][0]), "+f"(acc[mf][nf][1]),
                          "+f"(acc[mf][nf][2]), "+f"(acc[mf][nf][3])
                        : "r"(a[mf][0]), "r"(a[mf][1]), "r"(a[mf][2]), "r"(a[mf][3]),
                          "r"(b[nf].x), "r"(b[nf].y));
        }
        __syncthreads();
    }

    // ---- bias + store ----
    #pragma unroll
    for (int nf = 0; nf < 8; nf++) {
        int col = nw * 64 + nf * 8 + 2 * t;
        float2 bb = *reinterpret_cast<const float2*>(bv + col);
        #pragma unroll
        for (int mf = 0; mf < 2; mf++) {
            int r0 = row0 + mw * 32 + mf * 16 + g;
            if (r0 < n_rows) {
                float2 v = make_float2(acc[mf][nf][0] + bb.x, acc[mf][nf][1] + bb.y);
                *reinterpret_cast<float2*>(out + (size_t)r0 * F + col) = v;
            }
            if (r0 + 8 < n_rows) {
                float2 v = make_float2(acc[mf][nf][2] + bb.x, acc[mf][nf][3] + bb.y);
                *reinterpret_cast<float2*>(out + (size_t)(r0 + 8) * F + col) = v;
            }
        }
    }
}

// ---------------- f32x2 tiled linear (layer 3, exact fp32) ----------------
template <int F_IN, int F_OUT, int M_TILE, bool RELU_IN>
__global__ void __launch_bounds__(256, 2)
linear_tile_kernel(const float* __restrict__ in,
                   const float* __restrict__ Wm,
                   const float* __restrict__ bv,
                   float* __restrict__ out, int n_rows) {
    constexpr int MP2 = M_TILE / 2;
    constexpr int TX  = F_OUT / 8;
    constexpr int TY  = 256 / TX;
    static_assert(MP2 / TY == 4, "tile math");
    constexpr int GS  = 2 * TX;
    constexpr int CG  = 256 / MP2;
    constexpr int KPT = KC / CG;
    constexpr int C4  = F_IN / 4;

    __shared__ alignas(16) ull Hsu[KC][MP2];
    __shared__ alignas(16) ulonglong2 Ws2[KC][4][TX];

    const int tid  = threadIdx.x;
    const int row0 = blockIdx.x * M_TILE;
    const int tx   = tid % TX;
    const int ty   = tid / TX;

    ull acc[4][8];
    #pragma unroll
    for (int r = 0; r < 4; r++)
        #pragma unroll
        for (int c = 0; c < 8; c++) acc[r][c] = 0ull;

    const float4* in4 = reinterpret_cast<const float4*>(in);
    const int sp  = tid % MP2;
    const int scg = tid / MP2;
    const int ra  = row0 + 2 * sp;
    const int rb  = ra + 1;

    for (int kc = 0; kc < F_IN; kc += KC) {
        #pragma unroll
        for (int kk = 0; kk < KPT; kk += 4) {
            int k0 = scg * KPT + kk;
            float4 a = make_float4(0.f, 0.f, 0.f, 0.f);
            float4 b = make_float4(0.f, 0.f, 0.f, 0.f);
            if (ra < n_rows) a = in4[(size_t)ra * C4 + (kc + k0) / 4];
            if (rb < n_rows) b = in4[(size_t)rb * C4 + (kc + k0) / 4];
            if (RELU_IN) {
                a.x = fmaxf(a.x, 0.f); a.y = fmaxf(a.y, 0.f);
                a.z = fmaxf(a.z, 0.f); a.w = fmaxf(a.w, 0.f);
                b.x = fmaxf(b.x, 0.f); b.y = fmaxf(b.y, 0.f);
                b.z = fmaxf(b.z, 0.f); b.w = fmaxf(b.w, 0.f);
            }
            Hsu[k0 + 0][sp] = pack2(a.x, b.x);
            Hsu[k0 + 1][sp] = pack2(a.y, b.y);
            Hsu[k0 + 2][sp] = pack2(a.z, b.z);
            Hsu[k0 + 3][sp] = pack2(a.w, b.w);
        }
        #pragma unroll
        for (int idx = tid; idx < KC * 4 * TX; idx += 256) {
            int k   = idx / (4 * TX);
            int rem = idx - k * (4 * TX);
            int gq  = rem / TX;
            int tq  = rem - gq * TX;
            float2 wv = *reinterpret_cast<const float2*>(
                Wm + (size_t)(kc + k) * F_OUT + gq * GS + 2 * tq);
            ulonglong2 d2;
            d2.x = pack2(wv.x, wv.x);
            d2.y = pack2(wv.y, wv.y);
            Ws2[k][gq][tq] = d2;
        }
        __syncthreads();

        #pragma unroll 2
        for (int k = 0; k < KC; k++) {
            ulonglong2 h01 = *reinterpret_cast<const ulonglong2*>(&Hsu[k][ty * 4]);
            ulonglong2 h23 = *reinterpret_cast<const ulonglong2*>(&Hsu[k][ty * 4 + 2]);
            ulonglong2 w0 = Ws2[k][0][tx];
            ulonglong2 w1 = Ws2[k][1][tx];
            ulonglong2 w2 = Ws2[k][2][tx];
            ulonglong2 w3 = Ws2[k][3][tx];
            ull hr[4] = {h01.x, h01.y, h23.x, h23.y};
            ull wc[8] = {w0.x, w0.y, w1.x, w1.y, w2.x, w2.y, w3.x, w3.y};
            #pragma unroll
            for (int r = 0; r < 4; r++)
                #pragma unroll
                for (int c = 0; c < 8; c++)
                    asm("fma.rn.f32x2 %0, %1, %2, %0;"
                        : "+l"(acc[r][c]) : "l"(hr[r]), "l"(wc[c]));
        }
        __syncthreads();
    }

    float2 bb[4];
    #pragma unroll
    for (int gq = 0; gq < 4; gq++)
        bb[gq] = *reinterpret_cast<const float2*>(bv + gq * GS + 2 * tx);

    #pragma unroll
    for (int rp = 0; rp < 4; rp++) {
        int re = row0 + (ty * 4 + rp) * 2;
        #pragma unroll
        for (int gq = 0; gq < 4; gq++) {
            float2 c0 = *reinterpret_cast<float2*>(&acc[rp][2 * gq]);
            float2 c1 = *reinterpret_cast<float2*>(&acc[rp][2 * gq + 1]);
            int col = gq * GS + 2 * tx;
            if (re < n_rows) {
                float2 v = make_float2(c0.x + bb[gq].x, c1.x + bb[gq].y);
                *reinterpret_cast<float2*>(out + (size_t)re * F_OUT + col) = v;
            }
            if (re + 1 < n_rows) {
                float2 v = make_float2(c0.y + bb[gq].x, c1.y + bb[gq].y);
                *reinterpret_cast<float2*>(out + (size_t)(re + 1) * F_OUT + col) = v;
            }
        }
    }
}

// ---------------- gather aggregation (MLP=4, strided slots) ----------------
template <int F, bool ZERO_CUR>
__global__ void gather_kernel(const float* __restrict__ h,
                              float* __restrict__ out, int n_nodes) {
    constexpr int LANES = F / 4;
    const int tid = blockIdx.x * blockDim.x + threadIdx.x;
    const int node = tid / LANES;
    const int lane = tid - node * LANES;
    if (node >= n_nodes) return;

    const int wl = threadIdx.x & 31;
    const unsigned seg_mask = (LANES == 32) ? 0xffffffffu
                                            : (0xffffu << (wl & 16));

    int deg = __ldg(&g_cur[node]);
    if (deg > DEG_STRIDE) deg = DEG_STRIDE;
    if (ZERO_CUR && lane == 0) g_cur[node] = 0;
    const size_t beg = (size_t)node * DEG_STRIDE;
    const int cnt = deg < LANES ? deg : LANES;

    ull mymeta = 0;
    if (lane < cnt) mymeta = __ldg(&g_epack[beg + lane]);

    const float4* h4 = reinterpret_cast<const float4*>(h);
    float4 accA = make_float4(0.f, 0.f, 0.f, 0.f);
    float4 accB = make_float4(0.f, 0.f, 0.f, 0.f);

    int k = 0;
    for (; k + 4 <= cnt; k += 4) {
        ull m0 = __shfl_sync(seg_mask, mymeta, k + 0, LANES);
        ull m1 = __shfl_sync(seg_mask, mymeta, k + 1, LANES);
        ull m2 = __shfl_sync(seg_mask, mymeta, k + 2, LANES);
        ull m3 = __shfl_sync(seg_mask, mymeta, k + 3, LANES);
        float w0 = __uint_as_float((unsigned)(m0 >> 32));
        float w1 = __uint_as_float((unsigned)(m1 >> 32));
        float w2 = __uint_as_float((unsigned)(m2 >> 32));
        float w3 = __uint_as_float((unsigned)(m3 >> 32));
        float4 v0 = __ldg(h4 + (size_t)(unsigned)m0 * LANES + lane);
        float4 v1 = __ldg(h4 + (size_t)(unsigned)m1 * LANES + lane);
        float4 v2 = __ldg(h4 + (size_t)(unsigned)m2 * LANES + lane);
        float4 v3 = __ldg(h4 + (size_t)(unsigned)m3 * LANES + lane);
        accA.x += v0.x * w0; accA.y += v0.y * w0; accA.z += v0.z * w0; accA.w += v0.w * w0;
        accB.x += v1.x * w1; accB.y += v1.y * w1; accB.z += v1.z * w1; accB.w += v1.w * w1;
        accA.x += v2.x * w2; accA.y += v2.y * w2; accA.z += v2.z * w2; accA.w += v2.w * w2;
        accB.x += v3.x * w3; accB.y += v3.y * w3; accB.z += v3.z * w3; accB.w += v3.w * w3;
    }
    for (; k < cnt; k++) {
        ull m = __shfl_sync(seg_mask, mymeta, k, LANES);
        float w0 = __uint_as_float((unsigned)(m >> 32));
        float4 v0 = __ldg(h4 + (size_t)(unsigned)m * LANES + lane);
        accA.x += v0.x * w0; accA.y += v0.y * w0;
        accA.z += v0.z * w0; accA.w += v0.w * w0;
    }
    for (int j = LANES; j < deg; j++) {
        ull m = __ldg(&g_epack[beg + j]);
        float w0 = __uint_as_float((unsigned)(m >> 32));
        float4 v0 = __ldg(h4 + (size_t)(unsigned)m * LANES + lane);
        accB.x += v0.x * w0; accB.y += v0.y * w0;
        accB.z += v0.z * w0; accB.w += v0.w * w0;
    }

    accA.x += accB.x; accA.y += accB.y; accA.z += accB.z; accA.w += accB.w;
    reinterpret_cast<float4*>(out)[(size_t)node * LANES + lane] = accA;
}

extern "C" void kernel_launch(void* const* d_in, const int* in_sizes, int n_in,
                              void* d_out, int out_size) {
    const float* x   = (const float*)d_in[0];
    const float* w   = (const float*)d_in[1];
    const int*   src = (const int*)d_in[2];
    const int*   dst = (const int*)d_in[3];
    const float* W1  = (const float*)d_in[4];
    const float* b1  = (const float*)d_in[5];
    const float* W2  = (const float*)d_in[6];
    const float* b2  = (const float*)d_in[7];
    const float* W3  = (const float*)d_in[8];
    const float* b3  = (const float*)d_in[9];
    float* out = (float*)d_out;

    const int n_nodes = in_sizes[0] / IN_FEATS;
    const int n_edges = in_sizes[1];

    float *h_buf = nullptr, *agg_buf = nullptr;
    cudaGetSymbolAddress((void**)&h_buf, g_h);
    cudaGetSymbolAddress((void**)&agg_buf, g_agg);

    static cudaStream_t s2 = nullptr;
    static cudaEvent_t ev_fork = nullptr, ev_join = nullptr;
    if (!s2) {
        cudaStreamCreateWithFlags(&s2, cudaStreamNonBlocking);
        cudaEventCreateWithFlags(&ev_fork, cudaEventDisableTiming);
        cudaEventCreateWithFlags(&ev_join, cudaEventDisableTiming);
    }

    const int gemm128_blocks = (n_nodes + 127) / 128;
    const int gemm64_blocks  = (n_nodes + 255) / 256;
    const int g128_blocks = (n_nodes * (N_HIDDEN / 4) + 255) / 256;
    const int g64_blocks  = (n_nodes * (N_CLASSES / 4) + 255) / 256;
    const int bin_blocks  = ((n_edges + 3) / 4 + 255) / 256;

    cudaEventRecord(ev_fork, 0);
    cudaStreamWaitEvent(s2, ev_fork, 0);

    bin_kernel<<<bin_blocks, 256, 0, s2>>>(dst, src, w, n_edges);            // 1

    linear_tf32_kernel<false>
        <<<gemm128_blocks, 256>>>(x, W1, b1, h_buf, n_nodes);                // 2

    cudaEventRecord(ev_join, s2);
    cudaStreamWaitEvent(0, ev_join, 0);

    gather_kernel<N_HIDDEN, false><<<g128_blocks, 256>>>(h_buf, agg_buf, n_nodes);  // 3

    linear_tf32_kernel<true>
        <<<gemm128_blocks, 256>>>(agg_buf, W2, b2, h_buf, n_nodes);          // 4 <- profiled
    gather_kernel<N_HIDDEN, false><<<g128_blocks, 256>>>(h_buf, agg_buf, n_nodes);  // 5

    linear_tile_kernel<N_HIDDEN, N_CLASSES, 256, true>
        <<<gemm64_blocks, 256>>>(agg_buf, W3, b3, h_buf, n_nodes);           // 6
    gather_kernel<N_CLASSES, true><<<g64_blocks, 256>>>(h_buf, out, n_nodes);       // 7 (zeroes g_cur)
}

// round 13
// speedup vs baseline: 2.8241x; 1.1644x over previous
#include <cuda_runtime.h>
#include <cuda_fp16.h>
#include <cstdint>

#define N_NODES_MAX 50000
#define IN_FEATS 128
#define N_HIDDEN 128
#define N_CLASSES 64
#define DEG_STRIDE 96
#define KC 32
#define HS_STRIDE 44   // bank-conflict-free for STS.128 staging + frag LDS

typedef unsigned long long ull;

__device__ float g_h[N_NODES_MAX * N_HIDDEN];    // half for layers 1-2, float for layer 3
__device__ float g_agg[N_NODES_MAX * N_HIDDEN];
__device__ int   g_cur[N_NODES_MAX];
__device__ ull   g_epack[(size_t)N_NODES_MAX * DEG_STRIDE];

__device__ __forceinline__ ull pack_edge(int s, float w) {
    return ((ull)__float_as_uint(w) << 32) | (unsigned)s;
}
__device__ __forceinline__ unsigned to_tf32(float f) {
    unsigned u;
    asm("cvt.rna.tf32.f32 %0, %1;" : "=r"(u) : "f"(f));
    return u;
}

// ---------------- single-kernel CSR-lite build ----------------
__global__ void bin_kernel(const int* __restrict__ dst,
                           const int* __restrict__ src,
                           const float* __restrict__ w, int n_edges) {
    int t = blockIdx.x * blockDim.x + threadIdx.x;
    int e = t * 4;
    if (e + 4 <= n_edges) {
        int4 d = *reinterpret_cast<const int4*>(dst + e);
        int4 s = *reinterpret_cast<const int4*>(src + e);
        float4 ww = *reinterpret_cast<const float4*>(w + e);
        int p0 = atomicAdd(&g_cur[d.x], 1);
        int p1 = atomicAdd(&g_cur[d.y], 1);
        int p2 = atomicAdd(&g_cur[d.z], 1);
        int p3 = atomicAdd(&g_cur[d.w], 1);
        if (p0 < DEG_STRIDE) g_epack[(size_t)d.x * DEG_STRIDE + p0] = pack_edge(s.x, ww.x);
        if (p1 < DEG_STRIDE) g_epack[(size_t)d.y * DEG_STRIDE + p1] = pack_edge(s.y, ww.y);
        if (p2 < DEG_STRIDE) g_epack[(size_t)d.z * DEG_STRIDE + p2] = pack_edge(s.z, ww.z);
        if (p3 < DEG_STRIDE) g_epack[(size_t)d.w * DEG_STRIDE + p3] = pack_edge(s.w, ww.w);
    } else {
        for (int i = e; i < n_edges; i++) {
            int p = atomicAdd(&g_cur[dst[i]], 1);
            if (p < DEG_STRIDE) g_epack[(size_t)dst[i] * DEG_STRIDE + p] = pack_edge(src[i], w[i]);
        }
    }
}

// ---------------- tf32 tensor-core linear: 128-row tile, K = 128 ----------------
// NW = F_OUT/64. 8 warps: (8/NW) m-groups x NW n-groups; warp tile (16*NW)m x 64n.
// OutT: float or __half.
template <int NW, bool RELU_IN, typename OutT>
__global__ void __launch_bounds__(256, 2)
linear_tf32_kernel(const float* __restrict__ in,
                   const float* __restrict__ Wm,
                   const float* __restrict__ bv,
                   OutT* __restrict__ out, int n_rows) {
    constexpr int F_OUT = NW * 64;
    constexpr int MG = 8 / NW;                      // m-groups
    constexpr int MF = NW;                          // m-frags per warp
    __shared__ unsigned Hs[128 * HS_STRIDE];        // tf32 H tile, stride 44
    __shared__ uint2    Bf[4][NW * 8][32];          // B frags: [k8][n-frag][lane]

    const int tid  = threadIdx.x;
    const int row0 = blockIdx.x * 128;
    const int wid  = tid >> 5;
    const int lane = tid & 31;
    const int g    = lane >> 2;
    const int t    = lane & 3;
    const int mw   = wid % MG;
    const int nw   = wid / MG;

    float acc[MF][8][4];
    #pragma unroll
    for (int mf = 0; mf < MF; mf++)
        #pragma unroll
        for (int nf = 0; nf < 8; nf++)
            #pragma unroll
            for (int c = 0; c < 4; c++) acc[mf][nf][c] = 0.f;

    const float4* in4 = reinterpret_cast<const float4*>(in);

    for (int kc = 0; kc < 128; kc += KC) {
        // ---- stage H tile (coalesced LDG, ReLU + tf32 cvt, STS.128) ----
        #pragma unroll
        for (int i = 0; i < 4; i++) {
            int idx = tid + i * 256;               // 1024 float4 entries
            int c4  = idx & 7;
            int row = idx >> 3;
            float4 v = make_float4(0.f, 0.f, 0.f, 0.f);
            if (row0 + row < n_rows)
                v = in4[(size_t)(row0 + row) * 32 + (kc >> 2) + c4];
            if (RELU_IN) {
                v.x = fmaxf(v.x, 0.f); v.y = fmaxf(v.y, 0.f);
                v.z = fmaxf(v.z, 0.f); v.w = fmaxf(v.w, 0.f);
            }
            uint4 u;
            u.x = to_tf32(v.x); u.y = to_tf32(v.y);
            u.z = to_tf32(v.z); u.w = to_tf32(v.w);
            *reinterpret_cast<uint4*>(&Hs[row * HS_STRIDE + c4 * 4]) = u;
        }
        // ---- stage B frags ----
        #pragma unroll
        for (int i = 0; i < 4 * NW; i++) {
            int idx = tid + i * 256;               // 1024*NW entries
            int ln  = idx & 31;
            int nf  = (idx >> 5) % (NW * 8);
            int kk  = idx / (32 * NW * 8);
            int gg  = ln >> 2, tt = ln & 3;
            int krow = kc + kk * 8 + tt;
            int col  = nf * 8 + gg;
            uint2 b;
            b.x = to_tf32(__ldg(Wm + (size_t)krow * F_OUT + col));
            b.y = to_tf32(__ldg(Wm + (size_t)(krow + 4) * F_OUT + col));
            Bf[kk][nf][ln] = b;
        }
        __syncthreads();

        // ---- compute ----
        #pragma unroll
        for (int kk = 0; kk < 4; kk++) {
            unsigned a[MF][4];
            #pragma unroll
            for (int mf = 0; mf < MF; mf++) {
                int mbase = (mw * 16 * NW + mf * 16 + g) * HS_STRIDE + kk * 8;
                a[mf][0] = Hs[mbase + t];
                a[mf][1] = Hs[mbase + 8 * HS_STRIDE + t];
                a[mf][2] = Hs[mbase + t + 4];
                a[mf][3] = Hs[mbase + 8 * HS_STRIDE + t + 4];
            }
            uint2 b[8];
            #pragma unroll
            for (int nf = 0; nf < 8; nf++) b[nf] = Bf[kk][nw * 8 + nf][lane];
            #pragma unroll
            for (int mf = 0; mf < MF; mf++)
                #pragma unroll
                for (int nf = 0; nf < 8; nf++)
                    asm volatile(
                        "mma.sync.aligned.m16n8k8.row.col.f32.tf32.tf32.f32 "
                        "{%0,%1,%2,%3}, {%4,%5,%6,%7}, {%8,%9}, {%0,%1,%2,%3};\n"
                        : "+f"(acc[mf][nf][0]), "+f"(acc[mf][nf][1]),
                          "+f"(acc[mf][nf][2]), "+f"(acc[mf][nf][3])
                        : "r"(a[mf][0]), "r"(a[mf][1]), "r"(a[mf][2]), "r"(a[mf][3]),
                          "r"(b[nf].x), "r"(b[nf].y));
        }
        __syncthreads();
    }

    // ---- bias + store ----
    #pragma unroll
    for (int nf = 0; nf < 8; nf++) {
        int col = nw * 64 + nf * 8 + 2 * t;
        float2 bb = *reinterpret_cast<const float2*>(bv + col);
        #pragma unroll
        for (int mf = 0; mf < MF; mf++) {
            int r0 = row0 + mw * 16 * NW + mf * 16 + g;
            if (r0 < n_rows) {
                float vx = acc[mf][nf][0] + bb.x, vy = acc[mf][nf][1] + bb.y;
                if constexpr (sizeof(OutT) == 2) {
                    *reinterpret_cast<__half2*>(out + (size_t)r0 * F_OUT + col) =
                        __floats2half2_rn(vx, vy);
                } else {
                    *reinterpret_cast<float2*>(
                        reinterpret_cast<float*>(out) + (size_t)r0 * F_OUT + col) =
                        make_float2(vx, vy);
                }
            }
            if (r0 + 8 < n_rows) {
                float vx = acc[mf][nf][2] + bb.x, vy = acc[mf][nf][3] + bb.y;
                if constexpr (sizeof(OutT) == 2) {
                    *reinterpret_cast<__half2*>(out + (size_t)(r0 + 8) * F_OUT + col) =
                        __floats2half2_rn(vx, vy);
                } else {
                    *reinterpret_cast<float2*>(
                        reinterpret_cast<float*>(out) + (size_t)(r0 + 8) * F_OUT + col) =
                        make_float2(vx, vy);
                }
            }
        }
    }
}

// ---------------- gather aggregation (MLP=4, strided slots) ----------------
// T = float (16B/lane loads) or __half (8B/lane loads, fp32 accumulate).
template <int F, bool ZERO_CUR, typename T>
__global__ void gather_kernel(const T* __restrict__ h,
                              float* __restrict__ out, int n_nodes) {
    constexpr int LANES = F / 4;
    const int tid = blockIdx.x * blockDim.x + threadIdx.x;
    const int node = tid / LANES;
    const int lane = tid - node * LANES;
    if (node >= n_nodes) return;

    const int wl = threadIdx.x & 31;
    const unsigned seg_mask = (LANES == 32) ? 0xffffffffu
                                            : (0xffffu << (wl & 16));

    int deg = __ldg(&g_cur[node]);
    if (deg > DEG_STRIDE) deg = DEG_STRIDE;
    if (ZERO_CUR && lane == 0) g_cur[node] = 0;
    const size_t beg = (size_t)node * DEG_STRIDE;
    const int cnt = deg < LANES ? deg : LANES;

    ull mymeta = 0;
    if (lane < cnt) mymeta = __ldg(&g_epack[beg + lane]);

    auto load4 = [&](unsigned srcn) -> float4 {
        if constexpr (sizeof(T) == 2) {
            uint2 u = __ldg(reinterpret_cast<const uint2*>(h) + (size_t)srcn * LANES + lane);
            float2 a = __half22float2(*reinterpret_cast<__half2*>(&u.x));
            float2 b = __half22float2(*reinterpret_cast<__half2*>(&u.y));
            return make_float4(a.x, a.y, b.x, b.y);
        } else {
            return __ldg(reinterpret_cast<const float4*>(h) + (size_t)srcn * LANES + lane);
        }
    };

    float4 accA = make_float4(0.f, 0.f, 0.f, 0.f);
    float4 accB = make_float4(0.f, 0.f, 0.f, 0.f);

    int k = 0;
    for (; k + 4 <= cnt; k += 4) {
        ull m0 = __shfl_sync(seg_mask, mymeta, k + 0, LANES);
        ull m1 = __shfl_sync(seg_mask, mymeta, k + 1, LANES);
        ull m2 = __shfl_sync(seg_mask, mymeta, k + 2, LANES);
        ull m3 = __shfl_sync(seg_mask, mymeta, k + 3, LANES);
        float w0 = __uint_as_float((unsigned)(m0 >> 32));
        float w1 = __uint_as_float((unsigned)(m1 >> 32));
        float w2 = __uint_as_float((unsigned)(m2 >> 32));
        float w3 = __uint_as_float((unsigned)(m3 >> 32));
        float4 v0 = load4((unsigned)m0);
        float4 v1 = load4((unsigned)m1);
        float4 v2 = load4((unsigned)m2);
        float4 v3 = load4((unsigned)m3);
        accA.x += v0.x * w0; accA.y += v0.y * w0; accA.z += v0.z * w0; accA.w += v0.w * w0;
        accB.x += v1.x * w1; accB.y += v1.y * w1; accB.z += v1.z * w1; accB.w += v1.w * w1;
        accA.x += v2.x * w2; accA.y += v2.y * w2; accA.z += v2.z * w2; accA.w += v2.w * w2;
        accB.x += v3.x * w3; accB.y += v3.y * w3; accB.z += v3.z * w3; accB.w += v3.w * w3;
    }
    for (; k < cnt; k++) {
        ull m = __shfl_sync(seg_mask, mymeta, k, LANES);
        float w0 = __uint_as_float((unsigned)(m >> 32));
        float4 v0 = load4((unsigned)m);
        accA.x += v0.x * w0; accA.y += v0.y * w0;
        accA.z += v0.z * w0; accA.w += v0.w * w0;
    }
    for (int j = LANES; j < deg; j++) {
        ull m = __ldg(&g_epack[beg + j]);
        float w0 = __uint_as_float((unsigned)(m >> 32));
        float4 v0 = load4((unsigned)m);
        accB.x += v0.x * w0; accB.y += v0.y * w0;
        accB.z += v0.z * w0; accB.w += v0.w * w0;
    }

    accA.x += accB.x; accA.y += accB.y; accA.z += accB.z; accA.w += accB.w;
    reinterpret_cast<float4*>(out)[(size_t)node * LANES + lane] = accA;
}

extern "C" void kernel_launch(void* const* d_in, const int* in_sizes, int n_in,
                              void* d_out, int out_size) {
    const float* x   = (const float*)d_in[0];
    const float* w   = (const float*)d_in[1];
    const int*   src = (const int*)d_in[2];
    const int*   dst = (const int*)d_in[3];
    const float* W1  = (const float*)d_in[4];
    const float* b1  = (const float*)d_in[5];
    const float* W2  = (const float*)d_in[6];
    const float* b2  = (const float*)d_in[7];
    const float* W3  = (const float*)d_in[8];
    const float* b3  = (const float*)d_in[9];
    float* out = (float*)d_out;

    const int n_nodes = in_sizes[0] / IN_FEATS;
    const int n_edges = in_sizes[1];

    float *h_buf = nullptr, *agg_buf = nullptr;
    cudaGetSymbolAddress((void**)&h_buf, g_h);
    cudaGetSymbolAddress((void**)&agg_buf, g_agg);
    __half* h_half = reinterpret_cast<__half*>(h_buf);

    static cudaStream_t s2 = nullptr;
    static cudaEvent_t ev_fork = nullptr, ev_join = nullptr;
    if (!s2) {
        cudaStreamCreateWithFlags(&s2, cudaStreamNonBlocking);
        cudaEventCreateWithFlags(&ev_fork, cudaEventDisableTiming);
        cudaEventCreateWithFlags(&ev_join, cudaEventDisableTiming);
    }

    const int gemm_blocks = (n_nodes + 127) / 128;
    const int g128_blocks = (n_nodes * (N_HIDDEN / 4) + 255) / 256;
    const int g64_blocks  = (n_nodes * (N_CLASSES / 4) + 255) / 256;
    const int bin_blocks  = ((n_edges + 3) / 4 + 255) / 256;

    cudaEventRecord(ev_fork, 0);
    cudaStreamWaitEvent(s2, ev_fork, 0);

    bin_kernel<<<bin_blocks, 256, 0, s2>>>(dst, src, w, n_edges);            // 1

    linear_tf32_kernel<2, false, __half>
        <<<gemm_blocks, 256>>>(x, W1, b1, h_half, n_nodes);                  // 2

    cudaEventRecord(ev_join, s2);
    cudaStreamWaitEvent(0, ev_join, 0);

    gather_kernel<N_HIDDEN, false, __half>
        <<<g128_blocks, 256>>>(h_half, agg_buf, n_nodes);                    // 3

    linear_tf32_kernel<2, true, __half>
        <<<gemm_blocks, 256>>>(agg_buf, W2, b2, h_half, n_nodes);            // 4 <- profiled
    gather_kernel<N_HIDDEN, false, __half>
        <<<g128_blocks, 256>>>(h_half, agg_buf, n_nodes);                    // 5

    linear_tf32_kernel<1, true, float>
        <<<gemm_blocks, 256>>>(agg_buf, W3, b3, h_buf, n_nodes);             // 6
    gather_kernel<N_CLASSES, true, float>
        <<<g64_blocks, 256>>>(h_buf, out, n_nodes);                          // 7 (zeroes g_cur)
}